// round 1
// baseline (speedup 1.0000x reference)
#include <cuda_runtime.h>
#include <cstdint>

#define Bn 64
#define Tn 2048
#define Dn 512
#define Un 32
#define FULLM 0xffffffffu

// ---------------- packed f32x2 FMA ----------------
__device__ __forceinline__ unsigned long long fma2(unsigned long long a,
                                                   unsigned long long b,
                                                   unsigned long long c) {
    unsigned long long d;
    asm("fma.rn.f32x2 %0, %1, %2, %3;" : "=l"(d) : "l"(a), "l"(b), "l"(c));
    return d;
}
__device__ __forceinline__ void unpack2(unsigned long long a, float& lo, float& hi) {
    asm("mov.b64 {%0, %1}, %2;" : "=f"(lo), "=f"(hi) : "l"(a));
}

// 16 MB logits scratch
__device__ float g_logits[(size_t)Bn * Tn * Un];

// ---------------- GEMM: logits = x @ W + bias ----------------
// grid 1024 blocks x 512 threads. Block covers 128 rows. Warp lanes = U (x loads broadcast).
// W transposed into smem [32][520] (pad kills bank conflicts). K packed in pairs for f32x2.
__global__ __launch_bounds__(512, 1) void gemm_kernel(const float* __restrict__ x,
                                                      const float* __restrict__ W,
                                                      const float* __restrict__ bias,
                                                      float* __restrict__ out) {
    extern __shared__ float sWt[]; // 32 * 520 floats
    int tid = threadIdx.x;
    for (int i = tid; i < Dn * Un; i += 512) {
        int k = i >> 5, u = i & 31;
        sWt[u * 520 + k] = W[i];
    }
    __syncthreads();

    int w = tid >> 5, u = tid & 31;
    int row0 = blockIdx.x * 128 + w * 8;

    unsigned long long acc[8];
#pragma unroll
    for (int r = 0; r < 8; r++) acc[r] = 0ull;

    const float* xb = x + (size_t)row0 * Dn;
    const float* wrow = sWt + u * 520;

    for (int k8 = 0; k8 < Dn; k8 += 8) {
        ulonglong2 w0 = *(const ulonglong2*)(wrow + k8);
        ulonglong2 w1 = *(const ulonglong2*)(wrow + k8 + 4);
#pragma unroll
        for (int r = 0; r < 8; r++) {
            const float* xr = xb + r * Dn + k8;
            ulonglong2 x0 = *(const ulonglong2*)(xr);
            ulonglong2 x1 = *(const ulonglong2*)(xr + 4);
            acc[r] = fma2(x0.x, w0.x, acc[r]);
            acc[r] = fma2(x0.y, w0.y, acc[r]);
            acc[r] = fma2(x1.x, w1.x, acc[r]);
            acc[r] = fma2(x1.y, w1.y, acc[r]);
        }
    }
    float bu = bias[u];
#pragma unroll
    for (int r = 0; r < 8; r++) {
        float lo, hi;
        unpack2(acc[r], lo, hi);
        out[(size_t)(row0 + r) * Un + u] = lo + hi + bu;
    }
}

// ---------------- Viterbi: one warp per batch ----------------
// smem: bp[2048][32] u8 (64KB) + chk[32][32] u8 (1KB) + anch[32] int
__global__ __launch_bounds__(32, 1) void viterbi_kernel(const float* __restrict__ logits,
                                                        const int* __restrict__ nwords,
                                                        const float* __restrict__ trans,
                                                        float* __restrict__ out,
                                                        int write_pred, int write_score,
                                                        long long score_off) {
    extern __shared__ unsigned char sm[];
    unsigned char* bp = sm;                      // 65536
    unsigned char* chk = sm + 65536;             // 1024
    int* anch = (int*)(sm + 65536 + 1024);       // 128

    const int j = threadIdx.x;
    const int b = blockIdx.x;
    int len = nwords[b];
    if (len < 1) len = 1;
    if (len > Tn) len = Tn;
    const int tmax = len - 1;

    const float* lg = logits + (size_t)b * Tn * Un;

    // trans column j in registers: tc[i] = trans[i][j]
    float tc[32];
#pragma unroll
    for (int i = 0; i < 32; i++) tc[i] = trans[i * Un + j];

    float alpha = lg[j]; // alpha0
    int comp = j;        // path composition: tag@t -> tag@last_anchor

    float lgA = 0.f, lgB = 0.f;
    if (tmax >= 1) {
        lgA = lg[Un + j];
        int t2 = (tmax >= 2) ? 2 : 1;
        lgB = lg[t2 * Un + j];
    }

    for (int t = 1; t <= tmax; t++) {
        int tn = t + 2;
        if (tn > tmax) tn = tmax;
        float lgN = lg[tn * Un + j]; // depth-2 prefetch

        float c[32];
        int id[32];
#pragma unroll
        for (int i = 0; i < 32; i++) {
            float a = __shfl_sync(FULLM, alpha, i);
            c[i] = a + tc[i];
            id[i] = i;
        }
        // tournament argmax, left (lower index) wins ties -> matches jnp.argmax
#pragma unroll
        for (int s = 1; s < 32; s <<= 1) {
#pragma unroll
            for (int i = 0; i < 32; i += (s << 1)) {
                if (c[i + s] > c[i]) { c[i] = c[i + s]; id[i] = id[i + s]; }
            }
        }
        alpha = c[0] + lgA;
        bp[t * 32 + j] = (unsigned char)id[0];
        comp = __shfl_sync(FULLM, comp, id[0]);
        if ((t & 63) == 0) {
            chk[(t >> 6) * 32 + j] = (unsigned char)comp;
            comp = j;
        }
        lgA = lgB;
        lgB = lgN;
    }
    __syncwarp();

    // warp argmax over final alpha, lowest-index tie-break
    float bv = alpha;
    int bi = j;
#pragma unroll
    for (int off = 16; off >= 1; off >>= 1) {
        float ov = __shfl_xor_sync(FULLM, bv, off);
        int oi = __shfl_xor_sync(FULLM, bi, off);
        if (ov > bv || (ov == bv && oi < bi)) { bv = ov; bi = oi; }
    }
    const int last_tag = bi;
    const float best_score = bv;

    if (write_pred) {
        const int nA = tmax >> 6;
        int topTag = __shfl_sync(FULLM, comp, last_tag); // tag @ nA*64
        if (j == 0) {
            anch[nA] = topTag;
            for (int cI = nA; cI >= 1; --cI) anch[cI - 1] = chk[cI * 32 + anch[cI]];
        }
        __syncwarp();

        // tail: pred[t] = last_tag for t >= tmax
        for (int t = tmax + j; t < Tn; t += 32)
            out[(size_t)b * Tn + t] = (float)last_tag;

        // parallel per-chunk backtrack (lane c handles t in (c*64, t_hi])
        if (j <= nA) {
            int thi = (j == nA) ? tmax : ((j + 1) << 6);
            int tg = (j == nA) ? last_tag : anch[j + 1];
            for (int tt = thi; tt > (j << 6); --tt) {
                tg = bp[tt * 32 + tg];
                out[(size_t)b * Tn + tt - 1] = (float)tg;
            }
        }
    }
    if (write_score && j == 0) out[score_off + b] = best_score;
}

// ---------------- launch ----------------
extern "C" void kernel_launch(void* const* d_in, const int* in_sizes, int n_in,
                              void* d_out, int out_size) {
    const float* x = (const float*)d_in[0];
    const int* nwords = (const int*)d_in[1];
    const float* W = (const float*)d_in[2];
    const float* trans = (const float*)d_in[3];
    const float* bias = (const float*)d_in[4];
    float* out = (float*)d_out;

    const int BT = Bn * Tn;
    int write_pred = 1, write_score = 0;
    long long score_off = BT;
    if (out_size >= BT + Bn) {
        write_score = 1;
    } else if (out_size == Bn) { // scores only
        write_pred = 0;
        write_score = 1;
        score_off = 0;
    }

    static float* logits_ptr = nullptr;
    if (!logits_ptr) cudaGetSymbolAddress((void**)&logits_ptr, g_logits);

    const int gemm_smem = 32 * 520 * 4;       // 66560
    const int vit_smem = 65536 + 1024 + 128;  // 66688
    cudaFuncSetAttribute(gemm_kernel, cudaFuncAttributeMaxDynamicSharedMemorySize, gemm_smem);
    cudaFuncSetAttribute(viterbi_kernel, cudaFuncAttributeMaxDynamicSharedMemorySize, vit_smem);

    gemm_kernel<<<(Bn * Tn) / 128, 512, gemm_smem>>>(x, W, bias, logits_ptr);
    viterbi_kernel<<<Bn, 32, vit_smem>>>(logits_ptr, nwords, trans, out,
                                         write_pred, write_score, score_off);
}

// round 3
// speedup vs baseline: 1.3383x; 1.3383x over previous
#include <cuda_runtime.h>
#include <cstdint>

#define Bn 64
#define Tn 2048
#define Dn 512
#define Un 32
#define FULLM 0xffffffffu

// ---------------- packed f32x2 FMA ----------------
__device__ __forceinline__ unsigned long long fma2(unsigned long long a,
                                                   unsigned long long b,
                                                   unsigned long long c) {
    unsigned long long d;
    asm("fma.rn.f32x2 %0, %1, %2, %3;" : "=l"(d) : "l"(a), "l"(b), "l"(c));
    return d;
}
__device__ __forceinline__ void unpack2(unsigned long long a, float& lo, float& hi) {
    asm("mov.b64 {%0, %1}, %2;" : "=f"(lo), "=f"(hi) : "l"(a));
}

// 16 MB logits scratch
__device__ float g_logits[(size_t)Bn * Tn * Un];

// ---------------- GEMM: logits = x @ W + bias ----------------
// grid 1024 blocks x 512 threads. Block covers 128 rows. Warp lanes = U (x loads broadcast).
// W transposed into smem [32][520] (pad kills bank conflicts). K packed in pairs for f32x2.
__global__ __launch_bounds__(512, 1) void gemm_kernel(const float* __restrict__ x,
                                                      const float* __restrict__ W,
                                                      const float* __restrict__ bias,
                                                      float* __restrict__ out) {
    extern __shared__ float sWt[]; // 32 * 520 floats
    int tid = threadIdx.x;
    for (int i = tid; i < Dn * Un; i += 512) {
        int k = i >> 5, u = i & 31;
        sWt[u * 520 + k] = W[i];
    }
    __syncthreads();

    int w = tid >> 5, u = tid & 31;
    int row0 = blockIdx.x * 128 + w * 8;

    unsigned long long acc[8];
#pragma unroll
    for (int r = 0; r < 8; r++) acc[r] = 0ull;

    const float* xb = x + (size_t)row0 * Dn;
    const float* wrow = sWt + u * 520;

    for (int k8 = 0; k8 < Dn; k8 += 8) {
        ulonglong2 w0 = *(const ulonglong2*)(wrow + k8);
        ulonglong2 w1 = *(const ulonglong2*)(wrow + k8 + 4);
#pragma unroll
        for (int r = 0; r < 8; r++) {
            const float* xr = xb + r * Dn + k8;
            ulonglong2 x0 = *(const ulonglong2*)(xr);
            ulonglong2 x1 = *(const ulonglong2*)(xr + 4);
            acc[r] = fma2(x0.x, w0.x, acc[r]);
            acc[r] = fma2(x0.y, w0.y, acc[r]);
            acc[r] = fma2(x1.x, w1.x, acc[r]);
            acc[r] = fma2(x1.y, w1.y, acc[r]);
        }
    }
    float bu = bias[u];
#pragma unroll
    for (int r = 0; r < 8; r++) {
        float lo, hi;
        unpack2(acc[r], lo, hi);
        out[(size_t)(row0 + r) * Un + u] = lo + hi + bu;
    }
}

// ---------------- Viterbi: one warp per batch ----------------
// smem: bp[2048][32] u8 (64KB) + chk[32][32] u8 (1KB) + anch[32] int + alpha dbuf 2x32 f32
__global__ __launch_bounds__(32, 1) void viterbi_kernel(const float* __restrict__ logits,
                                                        const int* __restrict__ nwords,
                                                        const float* __restrict__ trans,
                                                        float* __restrict__ out,
                                                        int write_pred, int write_score,
                                                        long long score_off) {
    extern __shared__ unsigned char sm[];
    unsigned char* bp = sm;                        // 65536
    unsigned char* chk = sm + 65536;               // 1024
    int* anch = (int*)(sm + 65536 + 1024);         // 128
    float* abuf = (float*)(sm + 65536 + 1024 + 128); // 256 (2 x 32 floats)

    const int j = threadIdx.x;
    const int b = blockIdx.x;
    int len = nwords[b];
    if (len < 1) len = 1;
    if (len > Tn) len = Tn;
    const int tmax = len - 1;

    const float* lg = logits + (size_t)b * Tn * Un;

    // trans column j in registers: tc[i] = trans[i][j]
    float tc[32];
#pragma unroll
    for (int i = 0; i < 32; i++) tc[i] = trans[i * Un + j];

    float alpha = lg[j]; // alpha0
    abuf[j] = alpha;     // slot 0 holds alpha(t=0)
    int comp = j;        // path composition: tag@t -> tag@last_anchor

    float lgA = 0.f, lgB = 0.f;
    if (tmax >= 1) {
        lgA = lg[Un + j];
        int t2 = (tmax >= 2) ? 2 : 1;
        lgB = lg[t2 * Un + j];
    }

    for (int t = 1; t <= tmax; t++) {
        int tn = t + 2;
        if (tn > tmax) tn = tmax;
        float lgN = lg[tn * Un + j]; // depth-2 prefetch

        __syncwarp();  // all lanes' alpha(t-1) STS visible
        const float4* ap = (const float4*)(abuf + ((t - 1) & 1) * 32);

        float v[32];
        int ix[32];
#pragma unroll
        for (int p = 0; p < 8; p++) {
            float4 q = ap[p];  // broadcast LDS.128, conflict-free
            v[4 * p + 0] = q.x + tc[4 * p + 0];
            v[4 * p + 1] = q.y + tc[4 * p + 1];
            v[4 * p + 2] = q.z + tc[4 * p + 2];
            v[4 * p + 3] = q.w + tc[4 * p + 3];
        }
#pragma unroll
        for (int i = 0; i < 32; i++) ix[i] = i;

        // value via FMNMX tree (short chain); index via parallel FSETP/SEL tree.
        // Strict '>' so lower index wins ties -> matches jnp.argmax.
#pragma unroll
        for (int s = 1; s < 32; s <<= 1) {
#pragma unroll
            for (int i = 0; i < 32; i += (s << 1)) {
                bool gt = v[i + s] > v[i];
                v[i] = fmaxf(v[i], v[i + s]);
                ix[i] = gt ? ix[i + s] : ix[i];
            }
        }

        alpha = v[0] + lgA;
        abuf[(t & 1) * 32 + j] = alpha;        // publish alpha(t) in other slot
        bp[t * 32 + j] = (unsigned char)ix[0];
        comp = __shfl_sync(FULLM, comp, ix[0]);
        if ((t & 63) == 0) {
            chk[(t >> 6) * 32 + j] = (unsigned char)comp;
            comp = j;
        }
        lgA = lgB;
        lgB = lgN;
    }
    __syncwarp();

    // warp argmax over final alpha, lowest-index tie-break
    float bv = alpha;
    int bi = j;
#pragma unroll
    for (int off = 16; off >= 1; off >>= 1) {
        float ov = __shfl_xor_sync(FULLM, bv, off);
        int oi = __shfl_xor_sync(FULLM, bi, off);
        if (ov > bv || (ov == bv && oi < bi)) { bv = ov; bi = oi; }
    }
    const int last_tag = bi;
    const float best_score = bv;

    if (write_pred) {
        const int nA = tmax >> 6;
        int topTag = __shfl_sync(FULLM, comp, last_tag); // tag @ nA*64
        if (j == 0) {
            anch[nA] = topTag;
            for (int cI = nA; cI >= 1; --cI) anch[cI - 1] = chk[cI * 32 + anch[cI]];
        }
        __syncwarp();

        // tail: pred[t] = last_tag for t >= tmax
        for (int t = tmax + j; t < Tn; t += 32)
            out[(size_t)b * Tn + t] = (float)last_tag;

        // parallel per-chunk backtrack (lane c handles t in (c*64, t_hi])
        if (j <= nA) {
            int thi = (j == nA) ? tmax : ((j + 1) << 6);
            int tg = (j == nA) ? last_tag : anch[j + 1];
            for (int tt = thi; tt > (j << 6); --tt) {
                tg = bp[tt * 32 + tg];
                out[(size_t)b * Tn + tt - 1] = (float)tg;
            }
        }
    }
    if (write_score && j == 0) out[score_off + b] = best_score;
}

// ---------------- launch ----------------
extern "C" void kernel_launch(void* const* d_in, const int* in_sizes, int n_in,
                              void* d_out, int out_size) {
    const float* x = (const float*)d_in[0];
    const int* nwords = (const int*)d_in[1];
    const float* W = (const float*)d_in[2];
    const float* trans = (const float*)d_in[3];
    const float* bias = (const float*)d_in[4];
    float* out = (float*)d_out;

    const int BT = Bn * Tn;
    int write_pred = 1, write_score = 0;
    long long score_off = BT;
    if (out_size >= BT + Bn) {
        write_score = 1;
    } else if (out_size == Bn) { // scores only
        write_pred = 0;
        write_score = 1;
        score_off = 0;
    }

    static float* logits_ptr = nullptr;
    if (!logits_ptr) cudaGetSymbolAddress((void**)&logits_ptr, g_logits);

    const int gemm_smem = 32 * 520 * 4;               // 66560
    const int vit_smem = 65536 + 1024 + 128 + 256;    // 66944
    cudaFuncSetAttribute(gemm_kernel, cudaFuncAttributeMaxDynamicSharedMemorySize, gemm_smem);
    cudaFuncSetAttribute(viterbi_kernel, cudaFuncAttributeMaxDynamicSharedMemorySize, vit_smem);

    gemm_kernel<<<(Bn * Tn) / 128, 512, gemm_smem>>>(x, W, bias, logits_ptr);
    viterbi_kernel<<<Bn, 32, vit_smem>>>(logits_ptr, nwords, trans, out,
                                         write_pred, write_score, score_off);
}

// round 5
// speedup vs baseline: 1.3416x; 1.0025x over previous
#include <cuda_runtime.h>
#include <cstdint>

#define Bn 64
#define Tn 2048
#define Dn 512
#define Un 32
#define FULLM 0xffffffffu

// ---------------- packed f32x2 ops ----------------
__device__ __forceinline__ unsigned long long fma2(unsigned long long a,
                                                   unsigned long long b,
                                                   unsigned long long c) {
    unsigned long long d;
    asm("fma.rn.f32x2 %0, %1, %2, %3;" : "=l"(d) : "l"(a), "l"(b), "l"(c));
    return d;
}
__device__ __forceinline__ unsigned long long add2(unsigned long long a,
                                                   unsigned long long b) {
    unsigned long long d;
    asm("add.rn.f32x2 %0, %1, %2;" : "=l"(d) : "l"(a), "l"(b));
    return d;
}
__device__ __forceinline__ void unpack2(unsigned long long a, float& lo, float& hi) {
    asm("mov.b64 {%0, %1}, %2;" : "=f"(lo), "=f"(hi) : "l"(a));
}
__device__ __forceinline__ unsigned long long pack2(float lo, float hi) {
    unsigned long long d;
    asm("mov.b64 %0, {%1, %2};" : "=l"(d) : "f"(lo), "f"(hi));
    return d;
}

// 16 MB logits scratch
__device__ float g_logits[(size_t)Bn * Tn * Un];

// ---------------- GEMM: logits = x @ W + bias ----------------
__global__ __launch_bounds__(512, 1) void gemm_kernel(const float* __restrict__ x,
                                                      const float* __restrict__ W,
                                                      const float* __restrict__ bias,
                                                      float* __restrict__ out) {
    extern __shared__ float sWt[]; // 32 * 520 floats
    int tid = threadIdx.x;
    for (int i = tid; i < Dn * Un; i += 512) {
        int k = i >> 5, u = i & 31;
        sWt[u * 520 + k] = W[i];
    }
    __syncthreads();

    int w = tid >> 5, u = tid & 31;
    int row0 = blockIdx.x * 128 + w * 8;

    unsigned long long acc[8];
#pragma unroll
    for (int r = 0; r < 8; r++) acc[r] = 0ull;

    const float* xb = x + (size_t)row0 * Dn;
    const float* wrow = sWt + u * 520;

    for (int k8 = 0; k8 < Dn; k8 += 8) {
        ulonglong2 w0 = *(const ulonglong2*)(wrow + k8);
        ulonglong2 w1 = *(const ulonglong2*)(wrow + k8 + 4);
#pragma unroll
        for (int r = 0; r < 8; r++) {
            const float* xr = xb + r * Dn + k8;
            ulonglong2 x0 = *(const ulonglong2*)(xr);
            ulonglong2 x1 = *(const ulonglong2*)(xr + 4);
            acc[r] = fma2(x0.x, w0.x, acc[r]);
            acc[r] = fma2(x0.y, w0.y, acc[r]);
            acc[r] = fma2(x1.x, w1.x, acc[r]);
            acc[r] = fma2(x1.y, w1.y, acc[r]);
        }
    }
    float bu = bias[u];
#pragma unroll
    for (int r = 0; r < 8; r++) {
        float lo, hi;
        unpack2(acc[r], lo, hi);
        out[(size_t)(row0 + r) * Un + u] = lo + hi + bu;
    }
}

// ---------------- Viterbi: one warp per batch ----------------
// smem: bp[2048][32] u8 (64KB) + chk[32][32] u8 (1KB) + anch[32] int + alpha dbuf 2x32 f32
__global__ __launch_bounds__(32, 1) void viterbi_kernel(const float* __restrict__ logits,
                                                        const int* __restrict__ nwords,
                                                        const float* __restrict__ trans,
                                                        float* __restrict__ out,
                                                        int write_pred, int write_score,
                                                        long long score_off) {
    extern __shared__ unsigned char sm[];
    unsigned char* bp = sm;                          // 65536
    unsigned char* chk = sm + 65536;                 // 1024
    int* anch = (int*)(sm + 65536 + 1024);           // 128
    float* abuf = (float*)(sm + 65536 + 1024 + 128); // 256 (2 x 32 floats)

    const int j = threadIdx.x;
    const int b = blockIdx.x;
    int len = nwords[b];
    if (len < 1) len = 1;
    if (len > Tn) len = Tn;
    const int tmax = len - 1;

    const float* lg = logits + (size_t)b * Tn * Un;

    // trans column j, packed in pairs: tcp[p] = (tc[2p], tc[2p+1])
    unsigned long long tcp[16];
#pragma unroll
    for (int p = 0; p < 16; p++)
        tcp[p] = pack2(trans[(2 * p) * Un + j], trans[(2 * p + 1) * Un + j]);

    float alpha = lg[j]; // alpha0
    abuf[j] = alpha;     // slot 0 holds alpha(t=0)
    int comp = j;        // path composition: tag@t -> tag@last_anchor

    float lgA = 0.f, lgB = 0.f;
    if (tmax >= 1) {
        lgA = lg[Un + j];
        int t2 = (tmax >= 2) ? 2 : 1;
        lgB = lg[t2 * Un + j];
    }

    for (int t = 1; t <= tmax; t++) {
        int tn = t + 2;
        if (tn > tmax) tn = tmax;
        float lgN = lg[tn * Un + j]; // depth-2 prefetch

        __syncwarp();  // all lanes' alpha(t-1) STS visible
        const ulonglong2* ap = (const ulonglong2*)(abuf + ((t - 1) & 1) * 32);

        // group-of-4 argmax as we load: only gv[8]/gi[8] stay live
        float gv[8];
        int gi[8];
#pragma unroll
        for (int p = 0; p < 8; p++) {
            ulonglong2 a2 = ap[p];                 // alpha[4p..4p+3], LDS.128 broadcast
            unsigned long long s0 = add2(a2.x, tcp[2 * p]);
            unsigned long long s1 = add2(a2.y, tcp[2 * p + 1]);
            float v0, v1, v2, v3;
            unpack2(s0, v0, v1);
            unpack2(s1, v2, v3);
            bool gA = v1 > v0;
            float m0 = fmaxf(v0, v1);
            int i0 = gA ? 4 * p + 1 : 4 * p;
            bool gB = v3 > v2;
            float m1 = fmaxf(v2, v3);
            int i1 = gB ? 4 * p + 3 : 4 * p + 2;
            bool gC = m1 > m0;
            gv[p] = fmaxf(m0, m1);
            gi[p] = gC ? i1 : i0;
        }
        // tree over 8 groups, left (lower index) wins ties -> matches jnp.argmax
#pragma unroll
        for (int s = 1; s < 8; s <<= 1) {
#pragma unroll
            for (int i = 0; i < 8; i += (s << 1)) {
                bool g = gv[i + s] > gv[i];
                gv[i] = fmaxf(gv[i], gv[i + s]);
                gi[i] = g ? gi[i + s] : gi[i];
            }
        }

        alpha = gv[0] + lgA;
        abuf[(t & 1) * 32 + j] = alpha;         // publish alpha(t) in other slot
        bp[t * 32 + j] = (unsigned char)gi[0];
        comp = __shfl_sync(FULLM, comp, gi[0]);
        if ((t & 63) == 0) {
            chk[(t >> 6) * 32 + j] = (unsigned char)comp;
            comp = j;
        }
        lgA = lgB;
        lgB = lgN;
    }
    __syncwarp();

    // warp argmax over final alpha, lowest-index tie-break
    float bv = alpha;
    int bi = j;
#pragma unroll
    for (int off = 16; off >= 1; off >>= 1) {
        float ov = __shfl_xor_sync(FULLM, bv, off);
        int oi = __shfl_xor_sync(FULLM, bi, off);
        if (ov > bv || (ov == bv && oi < bi)) { bv = ov; bi = oi; }
    }
    const int last_tag = bi;
    const float best_score = bv;

    if (write_pred) {
        const int nA = tmax >> 6;
        int topTag = __shfl_sync(FULLM, comp, last_tag); // tag @ nA*64
        if (j == 0) {
            anch[nA] = topTag;
            for (int cI = nA; cI >= 1; --cI) anch[cI - 1] = chk[cI * 32 + anch[cI]];
        }
        __syncwarp();

        // tail: pred[t] = last_tag for t >= tmax
        for (int t = tmax + j; t < Tn; t += 32)
            out[(size_t)b * Tn + t] = (float)last_tag;

        // parallel per-chunk backtrack (lane c handles t in (c*64, t_hi])
        if (j <= nA) {
            int thi = (j == nA) ? tmax : ((j + 1) << 6);
            int tg = (j == nA) ? last_tag : anch[j + 1];
            for (int tt = thi; tt > (j << 6); --tt) {
                tg = bp[tt * 32 + tg];
                out[(size_t)b * Tn + tt - 1] = (float)tg;
            }
        }
    }
    if (write_score && j == 0) out[score_off + b] = best_score;
}

// ---------------- launch ----------------
extern "C" void kernel_launch(void* const* d_in, const int* in_sizes, int n_in,
                              void* d_out, int out_size) {
    const float* x = (const float*)d_in[0];
    const int* nwords = (const int*)d_in[1];
    const float* W = (const float*)d_in[2];
    const float* trans = (const float*)d_in[3];
    const float* bias = (const float*)d_in[4];
    float* out = (float*)d_out;

    const int BT = Bn * Tn;
    int write_pred = 1, write_score = 0;
    long long score_off = BT;
    if (out_size >= BT + Bn) {
        write_score = 1;
    } else if (out_size == Bn) { // scores only
        write_pred = 0;
        write_score = 1;
        score_off = 0;
    }

    static float* logits_ptr = nullptr;
    if (!logits_ptr) cudaGetSymbolAddress((void**)&logits_ptr, g_logits);

    const int gemm_smem = 32 * 520 * 4;            // 66560
    const int vit_smem = 65536 + 1024 + 128 + 256; // 66944
    cudaFuncSetAttribute(gemm_kernel, cudaFuncAttributeMaxDynamicSharedMemorySize, gemm_smem);
    cudaFuncSetAttribute(viterbi_kernel, cudaFuncAttributeMaxDynamicSharedMemorySize, vit_smem);

    gemm_kernel<<<(Bn * Tn) / 128, 512, gemm_smem>>>(x, W, bias, logits_ptr);
    viterbi_kernel<<<Bn, 32, vit_smem>>>(logits_ptr, nwords, trans, out,
                                         write_pred, write_score, score_off);
}

// round 6
// speedup vs baseline: 2.4567x; 1.8311x over previous
#include <cuda_runtime.h>
#include <cstdint>

#define Bn 64
#define Tn 2048
#define Dn 512
#define Un 32
#define FULLM 0xffffffffu

// ---------------- packed f32x2 ops ----------------
__device__ __forceinline__ unsigned long long fma2(unsigned long long a,
                                                   unsigned long long b,
                                                   unsigned long long c) {
    unsigned long long d;
    asm("fma.rn.f32x2 %0, %1, %2, %3;" : "=l"(d) : "l"(a), "l"(b), "l"(c));
    return d;
}
__device__ __forceinline__ unsigned long long add2(unsigned long long a,
                                                   unsigned long long b) {
    unsigned long long d;
    asm("add.rn.f32x2 %0, %1, %2;" : "=l"(d) : "l"(a), "l"(b));
    return d;
}
__device__ __forceinline__ void unpack2(unsigned long long a, float& lo, float& hi) {
    asm("mov.b64 {%0, %1}, %2;" : "=f"(lo), "=f"(hi) : "l"(a));
}
__device__ __forceinline__ unsigned long long pack2(float lo, float hi) {
    unsigned long long d;
    asm("mov.b64 %0, {%1, %2};" : "=l"(d) : "f"(lo), "f"(hi));
    return d;
}

// 16 MB logits scratch
__device__ float g_logits[(size_t)Bn * Tn * Un];

// ---------------- GEMM v2: smem-staged x tiles ----------------
// 1024 blocks x 256 threads. Block = 128 rows. k in 4 tiles of 128.
// x tile staged coalesced (float4 LDG) into smem; compute reads broadcast LDS.128.
__global__ __launch_bounds__(256, 1) void gemm_kernel(const float* __restrict__ x,
                                                      const float* __restrict__ W,
                                                      const float* __restrict__ bias,
                                                      float* __restrict__ out) {
    extern __shared__ float smf[];
    float* sWt = smf;                 // 32 * 520
    float* sx = smf + 32 * 520;       // 128 * 132

    const int tid = threadIdx.x;
    // W transposed into smem [u][k], pad 520
    for (int i = tid; i < Dn * Un; i += 256) {
        int k = i >> 5, u = i & 31;
        sWt[u * 520 + k] = W[i];
    }

    const int row0 = blockIdx.x * 128;
    const int w = tid >> 5, u = tid & 31;
    const int wr0 = w * 16;

    unsigned long long acc[16];
#pragma unroll
    for (int r = 0; r < 16; r++) acc[r] = 0ull;

    for (int kt = 0; kt < 4; kt++) {
        // stage tile: 128 rows x 32 float4, coalesced
#pragma unroll 4
        for (int i = tid; i < 128 * 32; i += 256) {
            int r = i >> 5, kq = i & 31;
            float4 v = *(const float4*)(x + (size_t)(row0 + r) * Dn + kt * 128 + kq * 4);
            *(float4*)(sx + r * 132 + kq * 4) = v;
        }
        __syncthreads();   // stage (and W on first iter) complete

        for (int k8 = 0; k8 < 128; k8 += 8) {
            const float* wr = sWt + u * 520 + kt * 128 + k8;
            ulonglong2 w0 = *(const ulonglong2*)(wr);
            ulonglong2 w1 = *(const ulonglong2*)(wr + 4);
#pragma unroll
            for (int r = 0; r < 16; r++) {
                const float* xr = sx + (wr0 + r) * 132 + k8;
                ulonglong2 x0 = *(const ulonglong2*)(xr);
                ulonglong2 x1 = *(const ulonglong2*)(xr + 4);
                acc[r] = fma2(x0.x, w0.x, acc[r]);
                acc[r] = fma2(x0.y, w0.y, acc[r]);
                acc[r] = fma2(x1.x, w1.x, acc[r]);
                acc[r] = fma2(x1.y, w1.y, acc[r]);
            }
        }
        __syncthreads();   // computation done before next stage overwrites
    }

    float bu = bias[u];
#pragma unroll
    for (int r = 0; r < 16; r++) {
        float lo, hi;
        unpack2(acc[r], lo, hi);
        out[(size_t)(row0 + wr0 + r) * Un + u] = lo + hi + bu;
    }
}

// ---------------- Viterbi step ----------------
__device__ __forceinline__ void vstep(int t, float logit_t, float& alpha, int& comp,
                                      const unsigned long long* tcp, float* abuf,
                                      unsigned char* bp, unsigned char* chk, int j) {
    __syncwarp();  // previous step's alpha STS visible
    const ulonglong2* ap = (const ulonglong2*)(abuf + ((t - 1) & 1) * 32);

    float gv[8];
    int gi[8];
#pragma unroll
    for (int p = 0; p < 8; p++) {
        ulonglong2 a2 = ap[p];  // alpha[4p..4p+3], LDS.128 broadcast
        unsigned long long s0 = add2(a2.x, tcp[2 * p]);
        unsigned long long s1 = add2(a2.y, tcp[2 * p + 1]);
        float v0, v1, v2, v3;
        unpack2(s0, v0, v1);
        unpack2(s1, v2, v3);
        bool gA = v1 > v0;
        float m0 = fmaxf(v0, v1);
        int i0 = gA ? 4 * p + 1 : 4 * p;
        bool gB = v3 > v2;
        float m1 = fmaxf(v2, v3);
        int i1 = gB ? 4 * p + 3 : 4 * p + 2;
        bool gC = m1 > m0;
        gv[p] = fmaxf(m0, m1);
        gi[p] = gC ? i1 : i0;
    }
#pragma unroll
    for (int s = 1; s < 8; s <<= 1) {
#pragma unroll
        for (int i = 0; i < 8; i += (s << 1)) {
            bool g = gv[i + s] > gv[i];
            gv[i] = fmaxf(gv[i], gv[i + s]);
            gi[i] = g ? gi[i + s] : gi[i];
        }
    }

    alpha = gv[0] + logit_t;
    abuf[(t & 1) * 32 + j] = alpha;
    bp[t * 32 + j] = (unsigned char)gi[0];
    comp = __shfl_sync(FULLM, comp, gi[0]);
    if ((t & 63) == 0) {
        chk[(t >> 6) * 32 + j] = (unsigned char)comp;
        comp = j;
    }
}

__device__ __forceinline__ float ldclamp(const float* lg, int t, int tmax, int j) {
    int ti = t <= tmax ? t : tmax;
    return lg[ti * Un + j];
}

// ---------------- Viterbi: one warp per batch ----------------
__global__ __launch_bounds__(32, 1) void viterbi_kernel(const float* __restrict__ logits,
                                                        const int* __restrict__ nwords,
                                                        const float* __restrict__ trans,
                                                        float* __restrict__ out,
                                                        int write_pred, int write_score,
                                                        long long score_off) {
    extern __shared__ unsigned char sm[];
    unsigned char* bp = sm;                          // 65536
    unsigned char* chk = sm + 65536;                 // 1024
    int* anch = (int*)(sm + 65536 + 1024);           // 128
    float* abuf = (float*)(sm + 65536 + 1024 + 128); // 256 (2 x 32 floats)

    const int j = threadIdx.x;
    const int b = blockIdx.x;
    int len = nwords[b];
    if (len < 1) len = 1;
    if (len > Tn) len = Tn;
    const int tmax = len - 1;

    const float* lg = logits + (size_t)b * Tn * Un;

    // trans column j, packed in pairs: tcp[p] = (tc[2p], tc[2p+1])
    unsigned long long tcp[16];
#pragma unroll
    for (int p = 0; p < 16; p++)
        tcp[p] = pack2(trans[(2 * p) * Un + j], trans[(2 * p + 1) * Un + j]);

    float alpha = lg[j]; // alpha0
    abuf[j] = alpha;     // slot 0 holds alpha(t=0)
    int comp = j;        // path composition: tag@t -> tag@last_anchor

    // 4-deep rotating logit prefetch: pl[q] = logit[min(t+q, tmax)]
    float pl0 = ldclamp(lg, 1, tmax, j);
    float pl1 = ldclamp(lg, 2, tmax, j);
    float pl2 = ldclamp(lg, 3, tmax, j);
    float pl3 = ldclamp(lg, 4, tmax, j);

    int t = 1;
    for (; t + 3 <= tmax; t += 4) {
        // issue next 4 loads first: distance ~4 steps hides L2/DRAM latency
        float n0 = ldclamp(lg, t + 4, tmax, j);
        float n1 = ldclamp(lg, t + 5, tmax, j);
        float n2 = ldclamp(lg, t + 6, tmax, j);
        float n3 = ldclamp(lg, t + 7, tmax, j);
        vstep(t, pl0, alpha, comp, tcp, abuf, bp, chk, j);
        vstep(t + 1, pl1, alpha, comp, tcp, abuf, bp, chk, j);
        vstep(t + 2, pl2, alpha, comp, tcp, abuf, bp, chk, j);
        vstep(t + 3, pl3, alpha, comp, tcp, abuf, bp, chk, j);
        pl0 = n0; pl1 = n1; pl2 = n2; pl3 = n3;
    }
    for (; t <= tmax; t++) {
        vstep(t, pl0, alpha, comp, tcp, abuf, bp, chk, j);
        pl0 = pl1; pl1 = pl2; pl2 = pl3;
    }
    __syncwarp();

    // warp argmax over final alpha, lowest-index tie-break
    float bv = alpha;
    int bi = j;
#pragma unroll
    for (int off = 16; off >= 1; off >>= 1) {
        float ov = __shfl_xor_sync(FULLM, bv, off);
        int oi = __shfl_xor_sync(FULLM, bi, off);
        if (ov > bv || (ov == bv && oi < bi)) { bv = ov; bi = oi; }
    }
    const int last_tag = bi;
    const float best_score = bv;

    if (write_pred) {
        const int nA = tmax >> 6;
        int topTag = __shfl_sync(FULLM, comp, last_tag); // tag @ nA*64
        if (j == 0) {
            anch[nA] = topTag;
            for (int cI = nA; cI >= 1; --cI) anch[cI - 1] = chk[cI * 32 + anch[cI]];
        }
        __syncwarp();

        // tail: pred[t] = last_tag for t >= tmax
        for (int tt = tmax + j; tt < Tn; tt += 32)
            out[(size_t)b * Tn + tt] = (float)last_tag;

        // parallel per-chunk backtrack (lane c handles t in (c*64, t_hi])
        if (j <= nA) {
            int thi = (j == nA) ? tmax : ((j + 1) << 6);
            int tg = (j == nA) ? last_tag : anch[j + 1];
            for (int tt = thi; tt > (j << 6); --tt) {
                tg = bp[tt * 32 + tg];
                out[(size_t)b * Tn + tt - 1] = (float)tg;
            }
        }
    }
    if (write_score && j == 0) out[score_off + b] = best_score;
}

// ---------------- launch ----------------
extern "C" void kernel_launch(void* const* d_in, const int* in_sizes, int n_in,
                              void* d_out, int out_size) {
    const float* x = (const float*)d_in[0];
    const int* nwords = (const int*)d_in[1];
    const float* W = (const float*)d_in[2];
    const float* trans = (const float*)d_in[3];
    const float* bias = (const float*)d_in[4];
    float* out = (float*)d_out;

    const int BT = Bn * Tn;
    int write_pred = 1, write_score = 0;
    long long score_off = BT;
    if (out_size >= BT + Bn) {
        write_score = 1;
    } else if (out_size == Bn) { // scores only
        write_pred = 0;
        write_score = 1;
        score_off = 0;
    }

    static float* logits_ptr = nullptr;
    if (!logits_ptr) cudaGetSymbolAddress((void**)&logits_ptr, g_logits);

    const int gemm_smem = (32 * 520 + 128 * 132) * 4;  // 134144
    const int vit_smem = 65536 + 1024 + 128 + 256;     // 66944
    cudaFuncSetAttribute(gemm_kernel, cudaFuncAttributeMaxDynamicSharedMemorySize, gemm_smem);
    cudaFuncSetAttribute(viterbi_kernel, cudaFuncAttributeMaxDynamicSharedMemorySize, vit_smem);

    gemm_kernel<<<(Bn * Tn) / 128, 256, gemm_smem>>>(x, W, bias, logits_ptr);
    viterbi_kernel<<<Bn, 32, vit_smem>>>(logits_ptr, nwords, trans, out,
                                         write_pred, write_score, score_off);
}

// round 7
// speedup vs baseline: 3.0296x; 1.2332x over previous
#include <cuda_runtime.h>
#include <cstdint>

#define Bn 64
#define Tn 2048
#define Dn 512
#define Un 32
#define FULLM 0xffffffffu

// ---------------- packed f32x2 ops ----------------
__device__ __forceinline__ unsigned long long fma2(unsigned long long a,
                                                   unsigned long long b,
                                                   unsigned long long c) {
    unsigned long long d;
    asm("fma.rn.f32x2 %0, %1, %2, %3;" : "=l"(d) : "l"(a), "l"(b), "l"(c));
    return d;
}
__device__ __forceinline__ unsigned long long add2(unsigned long long a,
                                                   unsigned long long b) {
    unsigned long long d;
    asm("add.rn.f32x2 %0, %1, %2;" : "=l"(d) : "l"(a), "l"(b));
    return d;
}
__device__ __forceinline__ void unpack2(unsigned long long a, float& lo, float& hi) {
    asm("mov.b64 {%0, %1}, %2;" : "=f"(lo), "=f"(hi) : "l"(a));
}
__device__ __forceinline__ unsigned long long pack2(float lo, float hi) {
    unsigned long long d;
    asm("mov.b64 %0, {%1, %2};" : "=l"(d) : "f"(lo), "f"(hi));
    return d;
}

// 16 MB logits scratch
__device__ float g_logits[(size_t)Bn * Tn * Un];

// ---------------- GEMM v3: 512 threads, register-prefetched tiles ----------------
// 1024 blocks x 512 threads. Block = 128 rows, k in 4 tiles of 128.
// Tile kt+1 LDGs issue before computing kt (latency hidden by ~4K cyc of FMA).
__global__ __launch_bounds__(512, 1) void gemm_kernel(const float* __restrict__ x,
                                                      const float* __restrict__ W,
                                                      const float* __restrict__ bias,
                                                      float* __restrict__ out) {
    extern __shared__ float smf[];
    float* sWt = smf;            // 32 * 520
    float* sx = smf + 32 * 520;  // 128 * 132

    const int tid = threadIdx.x;
    for (int i = tid; i < Dn * Un; i += 512) {
        int k = i >> 5, u = i & 31;
        sWt[u * 520 + k] = W[i];
    }

    const int row0 = blockIdx.x * 128;
    const int w = tid >> 5, u = tid & 31;
    const int wr0 = w * 8;

    unsigned long long acc[8];
#pragma unroll
    for (int r = 0; r < 8; r++) acc[r] = 0ull;

    // prologue: stage tile 0
    float4 st[8];
#pragma unroll
    for (int q = 0; q < 8; q++)
        st[q] = *(const float4*)(x + (size_t)(row0 + w + q * 16) * Dn + u * 4);
#pragma unroll
    for (int q = 0; q < 8; q++)
        *(float4*)(sx + (w + q * 16) * 132 + u * 4) = st[q];
    __syncthreads();

    for (int kt = 0; kt < 4; kt++) {
        if (kt < 3) {  // issue next tile's LDGs now; consumed after compute
#pragma unroll
            for (int q = 0; q < 8; q++)
                st[q] = *(const float4*)(x + (size_t)(row0 + w + q * 16) * Dn +
                                         (kt + 1) * 128 + u * 4);
        }
        const float* wbase = sWt + u * 520 + kt * 128;
        for (int k8 = 0; k8 < 128; k8 += 8) {
            ulonglong2 w0 = *(const ulonglong2*)(wbase + k8);
            ulonglong2 w1 = *(const ulonglong2*)(wbase + k8 + 4);
#pragma unroll
            for (int r = 0; r < 8; r++) {
                const float* xr = sx + (wr0 + r) * 132 + k8;
                ulonglong2 x0 = *(const ulonglong2*)(xr);
                ulonglong2 x1 = *(const ulonglong2*)(xr + 4);
                acc[r] = fma2(x0.x, w0.x, acc[r]);
                acc[r] = fma2(x0.y, w0.y, acc[r]);
                acc[r] = fma2(x1.x, w1.x, acc[r]);
                acc[r] = fma2(x1.y, w1.y, acc[r]);
            }
        }
        __syncthreads();  // done reading sx
        if (kt < 3) {
#pragma unroll
            for (int q = 0; q < 8; q++)
                *(float4*)(sx + (w + q * 16) * 132 + u * 4) = st[q];
            __syncthreads();  // new tile visible
        }
    }

    float bu = bias[u];
#pragma unroll
    for (int r = 0; r < 8; r++) {
        float lo, hi;
        unpack2(acc[r], lo, hi);
        out[(size_t)(row0 + wr0 + r) * Un + u] = lo + hi + bu;
    }
}

// ---------------- Viterbi v3: 128 threads, quad-split i-reduction ----------------
// thread tid: j = tid>>2 (target tag), sub = tid&3 (i-range sub*8..sub*8+7)
__device__ __forceinline__ float ldclamp(const float* lg, int t, int tmax, int j) {
    int ti = t <= tmax ? t : tmax;
    return lg[ti * Un + j];
}

__device__ __forceinline__ void vstep(int t, float lgt, const unsigned long long* tcp,
                                      float* abuf, int* cbuf, unsigned char* bp,
                                      unsigned char* chk, int j, int sub) {
    __syncthreads();  // previous step's abuf/cbuf stores visible
    const ulonglong2* ap = (const ulonglong2*)(abuf + ((t - 1) & 1) * 32 + sub * 8);
    ulonglong2 a0 = ap[0];
    ulonglong2 a1 = ap[1];
    unsigned long long s0 = add2(a0.x, tcp[0]);
    unsigned long long s1 = add2(a0.y, tcp[1]);
    unsigned long long s2 = add2(a1.x, tcp[2]);
    unsigned long long s3 = add2(a1.y, tcp[3]);
    float v0, v1, v2, v3, v4, v5, v6, v7;
    unpack2(s0, v0, v1);
    unpack2(s1, v2, v3);
    unpack2(s2, v4, v5);
    unpack2(s3, v6, v7);
    const int ib = sub * 8;
    // 8 -> 1, strict '>' so lower index wins ties (matches jnp.argmax)
    bool gA = v1 > v0; float m01 = fmaxf(v0, v1); int i01 = gA ? ib + 1 : ib;
    bool gB = v3 > v2; float m23 = fmaxf(v2, v3); int i23 = gB ? ib + 3 : ib + 2;
    bool gC = v5 > v4; float m45 = fmaxf(v4, v5); int i45 = gC ? ib + 5 : ib + 4;
    bool gD = v7 > v6; float m67 = fmaxf(v6, v7); int i67 = gD ? ib + 7 : ib + 6;
    bool gE = m23 > m01; float mA = fmaxf(m01, m23); int iA = gE ? i23 : i01;
    bool gF = m67 > m45; float mB = fmaxf(m45, m67); int iB = gF ? i67 : i45;
    bool gG = mB > mA; float val = fmaxf(mA, mB); int idx = gG ? iB : iA;
    // quad merge (sub ranges ordered by sub, so (pv==val && pi<idx) keeps first occurrence)
#pragma unroll
    for (int d = 1; d <= 2; d <<= 1) {
        float pv = __shfl_xor_sync(FULLM, val, d);
        int pi = __shfl_xor_sync(FULLM, idx, d);
        bool take = (pv > val) || (pv == val && pi < idx);
        val = take ? pv : val;
        idx = take ? pi : idx;
    }
    if (sub == 0) {
        abuf[(t & 1) * 32 + j] = val + lgt;
        bp[t * 32 + j] = (unsigned char)idx;
        int pc = cbuf[((t - 1) & 1) * 32 + idx];
        if ((t & 63) == 0) {
            chk[(t >> 6) * 32 + j] = (unsigned char)pc;
            pc = j;
        }
        cbuf[(t & 1) * 32 + j] = pc;
    }
}

__global__ __launch_bounds__(128, 1) void viterbi_kernel(const float* __restrict__ logits,
                                                         const int* __restrict__ nwords,
                                                         const float* __restrict__ trans,
                                                         float* __restrict__ out,
                                                         int write_pred, int write_score,
                                                         long long score_off) {
    extern __shared__ unsigned char sm[];
    unsigned char* bp = sm;                           // 65536
    unsigned char* chk = sm + 65536;                  // 1024
    int* anch = (int*)(sm + 65536 + 1024);            // 128
    float* abuf = (float*)(sm + 65536 + 1024 + 128);  // 256 (2 x 32)
    int* cbuf = (int*)(sm + 65536 + 1024 + 128 + 256);// 256 (2 x 32)
    int* sfin = (int*)(sm + 65536 + 1024 + 128 + 512);// 8 (last_tag)

    const int tid = threadIdx.x;
    const int j = tid >> 2;
    const int sub = tid & 3;
    const int b = blockIdx.x;
    int len = nwords[b];
    if (len < 1) len = 1;
    if (len > Tn) len = Tn;
    const int tmax = len - 1;

    const float* lg = logits + (size_t)b * Tn * Un;

    // my 8 trans rows for column j, packed
    unsigned long long tcp[4];
#pragma unroll
    for (int p = 0; p < 4; p++)
        tcp[p] = pack2(trans[(sub * 8 + 2 * p) * Un + j],
                       trans[(sub * 8 + 2 * p + 1) * Un + j]);

    if (tid < 32) {
        abuf[tid] = lg[tid];  // alpha0
        cbuf[tid] = tid;      // comp0
    }
    __syncthreads();

    // 4-deep rotating logit prefetch
    float pl0 = ldclamp(lg, 1, tmax, j);
    float pl1 = ldclamp(lg, 2, tmax, j);
    float pl2 = ldclamp(lg, 3, tmax, j);
    float pl3 = ldclamp(lg, 4, tmax, j);

    int t = 1;
    for (; t + 3 <= tmax; t += 4) {
        float n0 = ldclamp(lg, t + 4, tmax, j);
        float n1 = ldclamp(lg, t + 5, tmax, j);
        float n2 = ldclamp(lg, t + 6, tmax, j);
        float n3 = ldclamp(lg, t + 7, tmax, j);
        vstep(t, pl0, tcp, abuf, cbuf, bp, chk, j, sub);
        vstep(t + 1, pl1, tcp, abuf, cbuf, bp, chk, j, sub);
        vstep(t + 2, pl2, tcp, abuf, cbuf, bp, chk, j, sub);
        vstep(t + 3, pl3, tcp, abuf, cbuf, bp, chk, j, sub);
        pl0 = n0; pl1 = n1; pl2 = n2; pl3 = n3;
    }
    for (; t <= tmax; t++) {
        vstep(t, pl0, tcp, abuf, cbuf, bp, chk, j, sub);
        pl0 = pl1; pl1 = pl2; pl2 = pl3;
    }
    __syncthreads();

    const int fslot = (tmax & 1) * 32;
    // warp 0: argmax over final alpha, lowest-index tie-break
    if (tid < 32) {
        float bv = abuf[fslot + tid];
        int bi = tid;
#pragma unroll
        for (int off = 16; off >= 1; off >>= 1) {
            float ov = __shfl_xor_sync(FULLM, bv, off);
            int oi = __shfl_xor_sync(FULLM, bi, off);
            if (ov > bv || (ov == bv && oi < bi)) { bv = ov; bi = oi; }
        }
        if (tid == 0) {
            sfin[0] = bi;
            if (write_score) out[score_off + b] = bv;
        }
    }
    __syncthreads();
    const int last_tag = sfin[0];

    if (write_pred) {
        const int nA = tmax >> 6;
        if (tid == 0) {
            anch[nA] = cbuf[fslot + last_tag];  // tag @ nA*64
            for (int cI = nA; cI >= 1; --cI) anch[cI - 1] = chk[cI * 32 + anch[cI]];
        }
        // tail: pred[t] = last_tag for t >= tmax
        for (int tt = tmax + tid; tt < Tn; tt += 128)
            out[(size_t)b * Tn + tt] = (float)last_tag;
        __syncthreads();

        // parallel per-chunk backtrack (lane c handles t in (c*64, t_hi])
        if (tid <= nA) {
            int thi = (tid == nA) ? tmax : ((tid + 1) << 6);
            int tg = (tid == nA) ? last_tag : anch[tid + 1];
            for (int tt = thi; tt > (tid << 6); --tt) {
                tg = bp[tt * 32 + tg];
                out[(size_t)b * Tn + tt - 1] = (float)tg;
            }
        }
    }
}

// ---------------- launch ----------------
extern "C" void kernel_launch(void* const* d_in, const int* in_sizes, int n_in,
                              void* d_out, int out_size) {
    const float* x = (const float*)d_in[0];
    const int* nwords = (const int*)d_in[1];
    const float* W = (const float*)d_in[2];
    const float* trans = (const float*)d_in[3];
    const float* bias = (const float*)d_in[4];
    float* out = (float*)d_out;

    const int BT = Bn * Tn;
    int write_pred = 1, write_score = 0;
    long long score_off = BT;
    if (out_size >= BT + Bn) {
        write_score = 1;
    } else if (out_size == Bn) {  // scores only
        write_pred = 0;
        write_score = 1;
        score_off = 0;
    }

    static float* logits_ptr = nullptr;
    if (!logits_ptr) cudaGetSymbolAddress((void**)&logits_ptr, g_logits);

    const int gemm_smem = (32 * 520 + 128 * 132) * 4;        // 134144
    const int vit_smem = 65536 + 1024 + 128 + 256 + 256 + 8; // 67208
    cudaFuncSetAttribute(gemm_kernel, cudaFuncAttributeMaxDynamicSharedMemorySize, gemm_smem);
    cudaFuncSetAttribute(viterbi_kernel, cudaFuncAttributeMaxDynamicSharedMemorySize, vit_smem);

    gemm_kernel<<<(Bn * Tn) / 128, 512, gemm_smem>>>(x, W, bias, logits_ptr);
    viterbi_kernel<<<Bn, 128, vit_smem>>>(logits_ptr, nwords, trans, out,
                                          write_pred, write_score, score_off);
}